// round 1
// baseline (speedup 1.0000x reference)
#include <cuda_runtime.h>
#include <math.h>

#define N_TOT 4096
#define C_DIM 256
#define K_NEG 128
#define HW 1024
#define INV_T (1.0f / 0.07f)
#define NEG_INF (-1e30f)

// Scratch (allocation-free rule: __device__ globals)
__device__ float g_qn[N_TOT * C_DIM];   // normalized q, [N, C] contiguous
__device__ float g_kn[N_TOT * C_DIM];   // normalized k, [N, C] contiguous
__device__ float g_rowloss[N_TOT];

// ---------------------------------------------------------------------------
// Kernel 1: normalize over C and transpose [B,C,HW] -> [N,C] contiguous.
// grid = (128 n-tiles of 32, 2 tensors), block = (32, 8).
// ---------------------------------------------------------------------------
__global__ void __launch_bounds__(256) norm_transpose_kernel(
    const float* __restrict__ fq, const float* __restrict__ fk)
{
    const float* src = (blockIdx.y == 0) ? fq : fk;
    float* dst       = (blockIdx.y == 0) ? g_qn : g_kn;

    const int n0  = blockIdx.x * 32;      // 32 | 1024, tile never crosses batch
    const int b   = n0 / HW;
    const int hw0 = n0 % HW;
    const int tx  = threadIdx.x;          // 0..31 : hw within tile
    const int ty  = threadIdx.y;          // 0..7

    __shared__ float tile[C_DIM][33];     // [c][hw], padded
    __shared__ float ssq[8][32];
    __shared__ float sinv[32];

    const float* base = src + (size_t)b * C_DIM * HW + hw0 + tx;

    float acc = 0.f;
    #pragma unroll
    for (int cc = 0; cc < 32; cc++) {
        int c = cc * 8 + ty;
        float v = base[(size_t)c * HW];   // coalesced across tx
        tile[c][tx] = v;
        acc += v * v;
    }
    ssq[ty][tx] = acc;
    __syncthreads();

    if (ty == 0) {
        float s = 0.f;
        #pragma unroll
        for (int r = 0; r < 8; r++) s += ssq[r][tx];
        // 1 / max(||v||, 1e-12)  ==  rsqrt(max(ss, 1e-24))
        sinv[tx] = rsqrtf(fmaxf(s, 1e-24f));
    }
    __syncthreads();

    const int c = ty * 32 + tx;           // each thread owns one channel
    #pragma unroll
    for (int r = 0; r < 32; r++) {        // r = row (position) within tile
        dst[(size_t)(n0 + r) * C_DIM + c] = tile[c][r] * sinv[r];
    }
}

// ---------------------------------------------------------------------------
// Kernel 2: per-row gather-dot + logsumexp. One block (128 thr) per position n.
// Each warp handles 32 negatives; warp 0 also computes l_pos.
// ---------------------------------------------------------------------------
__global__ void __launch_bounds__(128) patchnce_main_kernel(
    const int* __restrict__ negs)
{
    const int n = blockIdx.x;
    const int tid  = threadIdx.x;
    const int lane = tid & 31;
    const int warp = tid >> 5;

    __shared__ float4 sq[64];             // q row, 256 floats
    __shared__ float  slog[136];          // 129 logits (0 = l_pos)
    __shared__ float  red[4];

    if (tid < 64) sq[tid] = ((const float4*)(g_qn + (size_t)n * C_DIM))[tid];
    __syncthreads();

    const float4 qa = sq[lane];
    const float4 qb = sq[lane + 32];
    const float4* __restrict__ kbase = (const float4*)g_kn;

    // l_pos (warp 0)
    if (warp == 0) {
        float4 ka = __ldg(kbase + (size_t)n * 64 + lane);
        float4 kb = __ldg(kbase + (size_t)n * 64 + 32 + lane);
        float d = qa.x*ka.x + qa.y*ka.y + qa.z*ka.z + qa.w*ka.w
                + qb.x*kb.x + qb.y*kb.y + qb.z*kb.z + qb.w*kb.w;
        #pragma unroll
        for (int o = 16; o > 0; o >>= 1) d += __shfl_xor_sync(0xffffffffu, d, o);
        if (lane == 0) slog[0] = d * INV_T;
    }

    // 32 negatives per warp
    #pragma unroll 4
    for (int j = 0; j < 32; j++) {
        const int m = warp * 32 + j;
        int idx = negs[(size_t)n * K_NEG + m];
        idx += (idx >= n) ? 1 : 0;        // self-exclusion shift
        float4 ka = __ldg(kbase + (size_t)idx * 64 + lane);
        float4 kb = __ldg(kbase + (size_t)idx * 64 + 32 + lane);
        float d = qa.x*ka.x + qa.y*ka.y + qa.z*ka.z + qa.w*ka.w
                + qb.x*kb.x + qb.y*kb.y + qb.z*kb.z + qb.w*kb.w;
        #pragma unroll
        for (int o = 16; o > 0; o >>= 1) d += __shfl_xor_sync(0xffffffffu, d, o);
        if (lane == 0) slog[1 + m] = d * INV_T;
    }
    __syncthreads();

    // logsumexp over 129 logits (128 threads; thread 0 also covers slog[128])
    const float x     = slog[tid];
    const float extra = (tid == 0) ? slog[128] : NEG_INF;

    float mx = fmaxf(x, extra);
    #pragma unroll
    for (int o = 16; o > 0; o >>= 1)
        mx = fmaxf(mx, __shfl_xor_sync(0xffffffffu, mx, o));
    if (lane == 0) red[warp] = mx;
    __syncthreads();
    mx = fmaxf(fmaxf(red[0], red[1]), fmaxf(red[2], red[3]));
    __syncthreads();                      // WAR on red[]

    float e = expf(x - mx) + ((tid == 0) ? expf(extra - mx) : 0.f);
    #pragma unroll
    for (int o = 16; o > 0; o >>= 1) e += __shfl_xor_sync(0xffffffffu, e, o);
    if (lane == 0) red[warp] = e;
    __syncthreads();

    if (tid == 0) {
        float s = red[0] + red[1] + red[2] + red[3];
        g_rowloss[n] = mx + logf(s) - slog[0];
    }
}

// ---------------------------------------------------------------------------
// Kernel 3: deterministic tree reduction of 4096 row losses -> mean.
// ---------------------------------------------------------------------------
__global__ void __launch_bounds__(256) finalize_kernel(float* __restrict__ out)
{
    __shared__ float s[256];
    const int tid = threadIdx.x;
    float a = 0.f;
    for (int i = tid; i < N_TOT; i += 256) a += g_rowloss[i];
    s[tid] = a;
    __syncthreads();
    #pragma unroll
    for (int stride = 128; stride > 0; stride >>= 1) {
        if (tid < stride) s[tid] += s[tid + stride];
        __syncthreads();
    }
    if (tid == 0) out[0] = s[0] * (1.0f / N_TOT);
}

// ---------------------------------------------------------------------------
extern "C" void kernel_launch(void* const* d_in, const int* in_sizes, int n_in,
                              void* d_out, int out_size)
{
    const float* fq   = (const float*)d_in[0];
    const float* fk   = (const float*)d_in[1];
    const int*   negs = (const int*)d_in[2];
    float*       out  = (float*)d_out;

    dim3 b1(32, 8);
    norm_transpose_kernel<<<dim3(128, 2), b1>>>(fq, fk);
    patchnce_main_kernel<<<N_TOT, 128>>>(negs);
    finalize_kernel<<<1, 256>>>(out);
}

// round 2
// speedup vs baseline: 1.4132x; 1.4132x over previous
#include <cuda_runtime.h>
#include <cuda_bf16.h>
#include <math.h>

#define N_TOT 4096
#define C_DIM 256
#define K_NEG 128
#define HW 1024
#define INV_T (1.0f / 0.07f)
#define NEG_INF (-1e30f)
#define FIX_SCALE 4294967296.0  // 2^32

// Scratch (allocation-free rule: __device__ globals)
__device__ __align__(16) __nv_bfloat16 g_qn[N_TOT * C_DIM];  // normalized q, [N,C]
__device__ __align__(16) __nv_bfloat16 g_kn[N_TOT * C_DIM];  // normalized k, [N,C]
__device__ unsigned long long g_acc;                          // fixed-point loss sum

// unpack one u32 holding 2 bf16 (little-endian: low 16 bits = even element)
__device__ __forceinline__ float2 bf2f(unsigned int u) {
    float2 r;
    r.x = __uint_as_float(u << 16);
    r.y = __uint_as_float(u & 0xffff0000u);
    return r;
}

// ---------------------------------------------------------------------------
// Kernel 1: normalize over C and transpose [B,C,HW] -> [N,C] bf16 contiguous.
// grid = (256 n-tiles of 16, 2 tensors), block = (16, 16).
// ---------------------------------------------------------------------------
__global__ void __launch_bounds__(256) norm_transpose_kernel(
    const float* __restrict__ fq, const float* __restrict__ fk)
{
    // zero the fixed-point accumulator once per launch (before main kernel)
    if (blockIdx.x == 0 && blockIdx.y == 0 && threadIdx.x == 0 && threadIdx.y == 0)
        g_acc = 0ull;

    const float* src      = (blockIdx.y == 0) ? fq : fk;
    __nv_bfloat16* dst    = (blockIdx.y == 0) ? g_qn : g_kn;

    const int n0  = blockIdx.x * 16;      // 16 | 1024, tile never crosses batch
    const int b   = n0 / HW;
    const int hw0 = n0 % HW;
    const int tx  = threadIdx.x;          // 0..15 : hw within tile
    const int ty  = threadIdx.y;          // 0..15

    __shared__ float tile[C_DIM][17];     // [c][hw], padded
    __shared__ float ssq[16][16];
    __shared__ float sinv[16];

    const float* base = src + (size_t)b * C_DIM * HW + hw0 + tx;

    float acc = 0.f;
    #pragma unroll
    for (int cc = 0; cc < 16; cc++) {
        int c = cc * 16 + ty;
        float v = base[(size_t)c * HW];   // 64B coalesced across tx
        tile[c][tx] = v;
        acc += v * v;
    }
    ssq[ty][tx] = acc;
    __syncthreads();

    if (ty == 0) {
        float s = 0.f;
        #pragma unroll
        for (int r = 0; r < 16; r++) s += ssq[r][tx];
        sinv[tx] = rsqrtf(fmaxf(s, 1e-24f));  // 1/max(||v||,1e-12)
    }
    __syncthreads();

    const int c = ty * 16 + tx;           // thread owns one channel == linear tid
    #pragma unroll
    for (int r = 0; r < 16; r++) {
        dst[(size_t)(n0 + r) * C_DIM + c] =
            __float2bfloat16_rn(tile[c][r] * sinv[r]);
    }
}

// ---------------------------------------------------------------------------
// Kernel 2: per-row gather-dot (bf16 k-table) + logsumexp.
// One block (128 thr) per position n; each warp handles 32 negatives; a
// gathered k row is 512B = one uint4 per lane. Partial dots reduced via a
// shared-memory transpose (no shuffle chains).
// ---------------------------------------------------------------------------
__global__ void __launch_bounds__(128) patchnce_main_kernel(
    const int* __restrict__ negs)
{
    const int n    = blockIdx.x;
    const int tid  = threadIdx.x;
    const int lane = tid & 31;
    const int warp = tid >> 5;

    __shared__ uint4 sq4[32];             // q row: 256 bf16 = 512 B
    __shared__ float part[4][32][33];     // [warp][neg][lane], padded
    __shared__ float slog[132];           // 129 logits (0 = l_pos)
    __shared__ float red[4];

    const uint4* __restrict__ kbase = (const uint4*)g_kn;

    if (tid < 32) sq4[tid] = ((const uint4*)(g_qn + (size_t)n * C_DIM))[tid];
    __syncthreads();

    // unpack this lane's 8 q channels to fp32 regs
    const uint4 qv = sq4[lane];
    const float2 q0 = bf2f(qv.x), q1 = bf2f(qv.y),
                 q2 = bf2f(qv.z), q3 = bf2f(qv.w);

    // l_pos (warp 0, shuffle reduce — one-off)
    if (warp == 0) {
        uint4 kv = __ldg(kbase + (size_t)n * 32 + lane);
        float2 a0 = bf2f(kv.x), a1 = bf2f(kv.y), a2 = bf2f(kv.z), a3 = bf2f(kv.w);
        float d = q0.x*a0.x + q0.y*a0.y + q1.x*a1.x + q1.y*a1.y
                + q2.x*a2.x + q2.y*a2.y + q3.x*a3.x + q3.y*a3.y;
        #pragma unroll
        for (int o = 16; o > 0; o >>= 1) d += __shfl_xor_sync(0xffffffffu, d, o);
        if (lane == 0) slog[0] = d * INV_T;
    }

    // 32 negatives per warp: partials to smem
    const int* nrow = negs + (size_t)n * K_NEG + warp * 32;
    #pragma unroll 4
    for (int j = 0; j < 32; j++) {
        int idx = nrow[j];
        idx += (idx >= n) ? 1 : 0;        // self-exclusion shift
        uint4 kv = __ldg(kbase + (size_t)idx * 32 + lane);
        float2 a0 = bf2f(kv.x), a1 = bf2f(kv.y), a2 = bf2f(kv.z), a3 = bf2f(kv.w);
        float d = q0.x*a0.x + q0.y*a0.y + q1.x*a1.x + q1.y*a1.y
                + q2.x*a2.x + q2.y*a2.y + q3.x*a3.x + q3.y*a3.y;
        part[warp][j][lane] = d;
    }
    __syncwarp();

    // transpose reduce: lane l sums partials of negative l
    {
        float s = 0.f;
        #pragma unroll
        for (int r = 0; r < 32; r++) s += part[warp][lane][r];
        slog[1 + warp * 32 + lane] = s * INV_T;
    }
    __syncthreads();

    // logsumexp over 129 logits (thread 0 also covers slog[128])
    const float x     = slog[tid];
    const float extra = (tid == 0) ? slog[128] : NEG_INF;

    float mx = fmaxf(x, extra);
    #pragma unroll
    for (int o = 16; o > 0; o >>= 1)
        mx = fmaxf(mx, __shfl_xor_sync(0xffffffffu, mx, o));
    if (lane == 0) red[warp] = mx;
    __syncthreads();
    mx = fmaxf(fmaxf(red[0], red[1]), fmaxf(red[2], red[3]));
    __syncthreads();                      // WAR on red[]

    float e = expf(x - mx) + ((tid == 0) ? expf(extra - mx) : 0.f);
    #pragma unroll
    for (int o = 16; o > 0; o >>= 1) e += __shfl_xor_sync(0xffffffffu, e, o);
    if (lane == 0) red[warp] = e;
    __syncthreads();

    if (tid == 0) {
        float s = red[0] + red[1] + red[2] + red[3];
        float rowloss = mx + logf(s) - slog[0];   // >= 0 always
        // deterministic fixed-point accumulate (integer atomics commute)
        unsigned long long fx =
            (unsigned long long)llrintf(rowloss * (float)FIX_SCALE);
        atomicAdd(&g_acc, fx);
    }
}

// ---------------------------------------------------------------------------
// Kernel 3: convert fixed-point sum -> mean loss.
// ---------------------------------------------------------------------------
__global__ void finalize_kernel(float* __restrict__ out)
{
    out[0] = (float)((double)g_acc * (1.0 / FIX_SCALE) * (1.0 / N_TOT));
}

// ---------------------------------------------------------------------------
extern "C" void kernel_launch(void* const* d_in, const int* in_sizes, int n_in,
                              void* d_out, int out_size)
{
    const float* fq   = (const float*)d_in[0];
    const float* fk   = (const float*)d_in[1];
    const int*   negs = (const int*)d_in[2];
    float*       out  = (float*)d_out;

    norm_transpose_kernel<<<dim3(256, 2), dim3(16, 16)>>>(fq, fk);
    patchnce_main_kernel<<<N_TOT, 128>>>(negs);
    finalize_kernel<<<1, 1>>>(out);
}

// round 3
// speedup vs baseline: 1.5411x; 1.0905x over previous
#include <cuda_runtime.h>
#include <cuda_bf16.h>
#include <cuda_fp8.h>
#include <math.h>

#define N_TOT 4096
#define C_DIM 256
#define K_NEG 128
#define HW 1024
#define INV_T (1.0f / 0.07f)
#define K8_SCALE 16.0f                 // k table stored as fp8 of (k * 16)
#define NEG_SCALE (INV_T / K8_SCALE)   // logit scale for fp8 dots
#define NEG_INF (-1e30f)
#define FIX_SCALE 4294967296.0         // 2^32

// Scratch (allocation-free rule: __device__ globals)
__device__ __align__(16) __nv_bfloat16 g_qn[N_TOT * C_DIM];   // normalized q, bf16
__device__ __align__(16) __nv_bfloat16 g_knb[N_TOT * C_DIM];  // normalized k, bf16 (l_pos)
__device__ __align__(16) unsigned char g_kn8[N_TOT * C_DIM];  // normalized k*16, e4m3
__device__ unsigned long long g_acc;                          // fixed-point loss sum

// unpack one u32 holding 2 bf16
__device__ __forceinline__ float2 bf2f(unsigned int u) {
    float2 r;
    r.x = __uint_as_float(u << 16);
    r.y = __uint_as_float(u & 0xffff0000u);
    return r;
}
// unpack 2 packed e4m3 -> float2
__device__ __forceinline__ float2 f8x2(unsigned short s) {
    __half2_raw hr = __nv_cvt_fp8x2_to_halfraw2((__nv_fp8x2_storage_t)s, __NV_E4M3);
    __half2 h = *reinterpret_cast<__half2*>(&hr);
    return __half22float2(h);
}

// ---------------------------------------------------------------------------
// Kernel 1: normalize over C, transpose [B,C,HW] -> [N,C].
// y==0: q -> bf16.  y==1: k -> bf16 + fp8(*16).
// ---------------------------------------------------------------------------
__global__ void __launch_bounds__(256) norm_transpose_kernel(
    const float* __restrict__ fq, const float* __restrict__ fk)
{
    if (blockIdx.x == 0 && blockIdx.y == 0 && threadIdx.x == 0 && threadIdx.y == 0)
        g_acc = 0ull;

    const bool is_k  = (blockIdx.y != 0);
    const float* src = is_k ? fk : fq;

    const int n0  = blockIdx.x * 16;      // 16 | 1024, tile never crosses batch
    const int b   = n0 / HW;
    const int hw0 = n0 % HW;
    const int tx  = threadIdx.x;          // 0..15 : hw within tile
    const int ty  = threadIdx.y;          // 0..15

    __shared__ float tile[C_DIM][17];
    __shared__ float ssq[16][16];
    __shared__ float sinv[16];

    const float* base = src + (size_t)b * C_DIM * HW + hw0 + tx;

    float acc = 0.f;
    #pragma unroll
    for (int cc = 0; cc < 16; cc++) {
        int c = cc * 16 + ty;
        float v = base[(size_t)c * HW];
        tile[c][tx] = v;
        acc += v * v;
    }
    ssq[ty][tx] = acc;
    __syncthreads();

    if (ty == 0) {
        float s = 0.f;
        #pragma unroll
        for (int r = 0; r < 16; r++) s += ssq[r][tx];
        sinv[tx] = rsqrtf(fmaxf(s, 1e-24f));
    }
    __syncthreads();

    const int c = ty * 16 + tx;           // thread owns one channel == linear tid
    if (!is_k) {
        #pragma unroll
        for (int r = 0; r < 16; r++)
            g_qn[(size_t)(n0 + r) * C_DIM + c] =
                __float2bfloat16_rn(tile[c][r] * sinv[r]);
    } else {
        #pragma unroll
        for (int r = 0; r < 16; r++) {
            float v = tile[c][r] * sinv[r];
            g_knb[(size_t)(n0 + r) * C_DIM + c] = __float2bfloat16_rn(v);
            g_kn8[(size_t)(n0 + r) * C_DIM + c] =
                (unsigned char)__nv_cvt_float_to_fp8(v * K8_SCALE,
                                                     __NV_SATFINITE, __NV_E4M3);
        }
    }
}

// ---------------------------------------------------------------------------
// Kernel 2: per-row gather-dot (fp8 negatives, bf16 positive) + logsumexp.
// One block (128 thr) per position n; each warp handles 32 negatives; a
// gathered fp8 row is 256B = one uint2 per lane.
// ---------------------------------------------------------------------------
__global__ void __launch_bounds__(128) patchnce_main_kernel(
    const int* __restrict__ negs)
{
    const int n    = blockIdx.x;
    const int tid  = threadIdx.x;
    const int lane = tid & 31;
    const int warp = tid >> 5;

    __shared__ uint4 sq4[32];             // q row: 256 bf16 = 512 B
    __shared__ float part[4][32][33];     // [warp][neg][lane], padded
    __shared__ float slog[132];           // 129 logits (0 = l_pos)
    __shared__ float red[4];

    const uint2* __restrict__ k8base = (const uint2*)g_kn8;

    if (tid < 32) sq4[tid] = ((const uint4*)(g_qn + (size_t)n * C_DIM))[tid];
    __syncthreads();

    // this lane's 8 q channels (lane*8 .. lane*8+7) in fp32
    const uint4 qv = sq4[lane];
    const float2 q0 = bf2f(qv.x), q1 = bf2f(qv.y),
                 q2 = bf2f(qv.z), q3 = bf2f(qv.w);

    // l_pos (warp 0, bf16 k row — unweighted logit gets full bf16 accuracy)
    if (warp == 0) {
        uint4 kv = __ldg((const uint4*)(g_knb + (size_t)n * C_DIM) + lane);
        float2 a0 = bf2f(kv.x), a1 = bf2f(kv.y), a2 = bf2f(kv.z), a3 = bf2f(kv.w);
        float d = q0.x*a0.x + q0.y*a0.y + q1.x*a1.x + q1.y*a1.y
                + q2.x*a2.x + q2.y*a2.y + q3.x*a3.x + q3.y*a3.y;
        #pragma unroll
        for (int o = 16; o > 0; o >>= 1) d += __shfl_xor_sync(0xffffffffu, d, o);
        if (lane == 0) slog[0] = d * INV_T;
    }

    // 32 negatives per warp; indices fetched once, broadcast by shuffle
    int myidx = negs[(size_t)n * K_NEG + warp * 32 + lane];
    myidx += (myidx >= n) ? 1 : 0;        // self-exclusion shift

    #pragma unroll 4
    for (int j = 0; j < 32; j++) {
        const int idx = __shfl_sync(0xffffffffu, myidx, j);
        uint2 kv = __ldg(k8base + (size_t)idx * 32 + lane);
        float2 a0 = f8x2((unsigned short)(kv.x & 0xffffu));
        float2 a1 = f8x2((unsigned short)(kv.x >> 16));
        float2 a2 = f8x2((unsigned short)(kv.y & 0xffffu));
        float2 a3 = f8x2((unsigned short)(kv.y >> 16));
        float d = q0.x*a0.x + q0.y*a0.y + q1.x*a1.x + q1.y*a1.y
                + q2.x*a2.x + q2.y*a2.y + q3.x*a3.x + q3.y*a3.y;
        part[warp][j][lane] = d;
    }
    __syncwarp();

    // transpose reduce: lane l sums partials of negative l
    {
        float s = 0.f;
        #pragma unroll
        for (int r = 0; r < 32; r++) s += part[warp][lane][r];
        slog[1 + warp * 32 + lane] = s * NEG_SCALE;
    }
    __syncthreads();

    // logsumexp over 129 logits (thread 0 also covers slog[128])
    const float x     = slog[tid];
    const float extra = (tid == 0) ? slog[128] : NEG_INF;

    float mx = fmaxf(x, extra);
    #pragma unroll
    for (int o = 16; o > 0; o >>= 1)
        mx = fmaxf(mx, __shfl_xor_sync(0xffffffffu, mx, o));
    if (lane == 0) red[warp] = mx;
    __syncthreads();
    mx = fmaxf(fmaxf(red[0], red[1]), fmaxf(red[2], red[3]));
    __syncthreads();                      // WAR on red[]

    float e = expf(x - mx) + ((tid == 0) ? expf(extra - mx) : 0.f);
    #pragma unroll
    for (int o = 16; o > 0; o >>= 1) e += __shfl_xor_sync(0xffffffffu, e, o);
    if (lane == 0) red[warp] = e;
    __syncthreads();

    if (tid == 0) {
        float s = red[0] + red[1] + red[2] + red[3];
        float rowloss = mx + logf(s) - slog[0];   // >= 0 always
        unsigned long long fx =
            (unsigned long long)llrintf(rowloss * (float)FIX_SCALE);
        atomicAdd(&g_acc, fx);            // integer atomics commute: deterministic
    }
}

// ---------------------------------------------------------------------------
// Kernel 3: convert fixed-point sum -> mean loss.
// ---------------------------------------------------------------------------
__global__ void finalize_kernel(float* __restrict__ out)
{
    out[0] = (float)((double)g_acc * (1.0 / FIX_SCALE) * (1.0 / N_TOT));
}

// ---------------------------------------------------------------------------
extern "C" void kernel_launch(void* const* d_in, const int* in_sizes, int n_in,
                              void* d_out, int out_size)
{
    const float* fq   = (const float*)d_in[0];
    const float* fk   = (const float*)d_in[1];
    const int*   negs = (const int*)d_in[2];
    float*       out  = (float*)d_out;

    norm_transpose_kernel<<<dim3(256, 2), dim3(16, 16)>>>(fq, fk);
    patchnce_main_kernel<<<N_TOT, 128>>>(negs);
    finalize_kernel<<<1, 1>>>(out);
}

// round 4
// speedup vs baseline: 1.8890x; 1.2258x over previous
#include <cuda_runtime.h>
#include <cuda_bf16.h>
#include <math.h>

#define N_TOT 4096
#define C_DIM 256
#define K_NEG 128
#define HW 1024
#define INV_T (1.0f / 0.07f)
#define Q8 256.0f                        // int8 quant scale for both q and k
#define NEG_SCALE (INV_T / (Q8 * Q8))    // logit scale for int dots
#define NEG_INF (-1e30f)
#define FIX_SCALE 4294967296.0           // 2^32

// Scratch (allocation-free rule: __device__ globals)
__device__ __align__(16) __nv_bfloat16 g_qnb[N_TOT * C_DIM]; // q bf16 (l_pos)
__device__ __align__(16) __nv_bfloat16 g_knb[N_TOT * C_DIM]; // k bf16 (l_pos)
__device__ __align__(16) signed char   g_qn8[N_TOT * C_DIM]; // q int8*256
__device__ __align__(16) signed char   g_kn8[N_TOT * C_DIM]; // k int8*256
__device__ unsigned long long g_acc;                          // fixed-point loss sum
__device__ unsigned int       g_done;                         // block completion ctr

__device__ __forceinline__ float2 bf2f(unsigned int u) {
    float2 r;
    r.x = __uint_as_float(u << 16);
    r.y = __uint_as_float(u & 0xffff0000u);
    return r;
}
__device__ __forceinline__ signed char q8(float v) {
    int iv = __float2int_rn(v * Q8);
    iv = max(-127, min(127, iv));
    return (signed char)iv;
}

// ---------------------------------------------------------------------------
// Kernel 1: normalize over C, transpose [B,C,HW] -> [N,C]; emit bf16 + int8.
// ---------------------------------------------------------------------------
__global__ void __launch_bounds__(256) norm_transpose_kernel(
    const float* __restrict__ fq, const float* __restrict__ fk)
{
    if (blockIdx.x == 0 && blockIdx.y == 0 && threadIdx.x == 0 && threadIdx.y == 0)
        g_acc = 0ull;

    const bool is_k  = (blockIdx.y != 0);
    const float* src = is_k ? fk : fq;
    __nv_bfloat16* dstb = is_k ? g_knb : g_qnb;
    signed char*   dst8 = is_k ? g_kn8 : g_qn8;

    const int n0  = blockIdx.x * 16;      // 16 | 1024, tile never crosses batch
    const int b   = n0 / HW;
    const int hw0 = n0 % HW;
    const int tx  = threadIdx.x;          // 0..15 : hw within tile
    const int ty  = threadIdx.y;          // 0..15

    __shared__ float tile[C_DIM][17];
    __shared__ float ssq[16][16];
    __shared__ float sinv[16];

    const float* base = src + (size_t)b * C_DIM * HW + hw0 + tx;

    float acc = 0.f;
    #pragma unroll
    for (int cc = 0; cc < 16; cc++) {
        int c = cc * 16 + ty;
        float v = base[(size_t)c * HW];
        tile[c][tx] = v;
        acc += v * v;
    }
    ssq[ty][tx] = acc;
    __syncthreads();

    if (ty == 0) {
        float s = 0.f;
        #pragma unroll
        for (int r = 0; r < 16; r++) s += ssq[r][tx];
        sinv[tx] = rsqrtf(fmaxf(s, 1e-24f));
    }
    __syncthreads();

    const int c = ty * 16 + tx;           // thread owns one channel == linear tid
    #pragma unroll
    for (int r = 0; r < 16; r++) {
        float v = tile[c][r] * sinv[r];
        size_t o = (size_t)(n0 + r) * C_DIM + c;
        dstb[o] = __float2bfloat16_rn(v);
        dst8[o] = q8(v);
    }
}

// ---------------------------------------------------------------------------
// Kernel 2: per-row gather-dot (int8 dp4a negatives, bf16 positive) +
// logsumexp + fused final reduction.
// ---------------------------------------------------------------------------
__global__ void __launch_bounds__(128) patchnce_main_kernel(
    const int* __restrict__ negs, float* __restrict__ out)
{
    const int n    = blockIdx.x;
    const int tid  = threadIdx.x;
    const int lane = tid & 31;
    const int warp = tid >> 5;

    __shared__ uint2 sq8[32];             // q row int8: 256 B
    __shared__ int   part[4][32][33];     // [warp][neg][lane], padded
    __shared__ float slog[132];           // 129 logits (0 = l_pos)
    __shared__ float red[4];

    const uint2* __restrict__ k8base = (const uint2*)g_kn8;

    if (tid < 32) sq8[tid] = ((const uint2*)(g_qn8 + (size_t)n * C_DIM))[tid];
    __syncthreads();

    const uint2 qi = sq8[lane];           // this lane's 8 q channels, int8

    // l_pos (warp 0): full bf16 x bf16 accuracy for the unweighted logit
    if (warp == 0) {
        uint4 qv = __ldg((const uint4*)(g_qnb + (size_t)n * C_DIM) + lane);
        uint4 kv = __ldg((const uint4*)(g_knb + (size_t)n * C_DIM) + lane);
        float2 q0 = bf2f(qv.x), q1 = bf2f(qv.y), q2 = bf2f(qv.z), q3 = bf2f(qv.w);
        float2 a0 = bf2f(kv.x), a1 = bf2f(kv.y), a2 = bf2f(kv.z), a3 = bf2f(kv.w);
        float d = q0.x*a0.x + q0.y*a0.y + q1.x*a1.x + q1.y*a1.y
                + q2.x*a2.x + q2.y*a2.y + q3.x*a3.x + q3.y*a3.y;
        #pragma unroll
        for (int o = 16; o > 0; o >>= 1) d += __shfl_xor_sync(0xffffffffu, d, o);
        if (lane == 0) slog[0] = d * INV_T;
    }

    // 32 negatives per warp; indices fetched once, broadcast by shuffle
    int myidx = negs[(size_t)n * K_NEG + warp * 32 + lane];
    myidx += (myidx >= n) ? 1 : 0;        // self-exclusion shift

    #pragma unroll 8
    for (int j = 0; j < 32; j++) {
        const int idx = __shfl_sync(0xffffffffu, myidx, j);
        uint2 kv = __ldg(k8base + (size_t)idx * 32 + lane);
        int d = __dp4a((int)kv.x, (int)qi.x, 0);
        d     = __dp4a((int)kv.y, (int)qi.y, d);
        part[warp][j][lane] = d;
    }
    __syncwarp();

    // transpose reduce (exact int sum): lane l sums partials of negative l
    {
        int s = 0;
        #pragma unroll
        for (int r = 0; r < 32; r++) s += part[warp][lane][r];
        slog[1 + warp * 32 + lane] = (float)s * NEG_SCALE;
    }
    __syncthreads();

    // logsumexp over 129 logits (thread 0 also covers slog[128])
    const float x     = slog[tid];
    const float extra = (tid == 0) ? slog[128] : NEG_INF;

    float mx = fmaxf(x, extra);
    #pragma unroll
    for (int o = 16; o > 0; o >>= 1)
        mx = fmaxf(mx, __shfl_xor_sync(0xffffffffu, mx, o));
    if (lane == 0) red[warp] = mx;
    __syncthreads();
    mx = fmaxf(fmaxf(red[0], red[1]), fmaxf(red[2], red[3]));
    __syncthreads();                      // WAR on red[]

    float e = expf(x - mx) + ((tid == 0) ? expf(extra - mx) : 0.f);
    #pragma unroll
    for (int o = 16; o > 0; o >>= 1) e += __shfl_xor_sync(0xffffffffu, e, o);
    if (lane == 0) red[warp] = e;
    __syncthreads();

    if (tid == 0) {
        float s = red[0] + red[1] + red[2] + red[3];
        float rowloss = mx + logf(s) - slog[0];   // >= 0 always
        unsigned long long fx =
            (unsigned long long)llrintf(rowloss * (float)FIX_SCALE);
        atomicAdd(&g_acc, fx);            // integer atomics commute: deterministic
        __threadfence();
        unsigned int t = atomicAdd(&g_done, 1u);
        if (t == (unsigned int)(gridDim.x - 1)) {
            // all blocks' g_acc contributions are visible (acq via atomic order)
            unsigned long long total = atomicAdd(&g_acc, 0ull);
            out[0] = (float)((double)total * (1.0 / FIX_SCALE) * (1.0 / N_TOT));
            g_done = 0u;                  // reset for next graph replay
        }
    }
}

// ---------------------------------------------------------------------------
extern "C" void kernel_launch(void* const* d_in, const int* in_sizes, int n_in,
                              void* d_out, int out_size)
{
    const float* fq   = (const float*)d_in[0];
    const float* fk   = (const float*)d_in[1];
    const int*   negs = (const int*)d_in[2];
    float*       out  = (float*)d_out;

    norm_transpose_kernel<<<dim3(256, 2), dim3(16, 16)>>>(fq, fk);
    patchnce_main_kernel<<<N_TOT, 128>>>(negs, out);
}

// round 5
// speedup vs baseline: 1.8939x; 1.0026x over previous
#include <cuda_runtime.h>
#include <math.h>

#define N_TOT 4096
#define C_DIM 256
#define K_NEG 128
#define HW 1024
#define INV_T (1.0f / 0.07f)
#define Q8 256.0f                        // int8 quant scale for both q and k
#define NEG_SCALE (INV_T / (Q8 * Q8))    // logit scale for int dots
#define NEG_INF (-1e30f)
#define FIX_SCALE 4294967296.0           // 2^32

// Scratch (allocation-free rule: __device__ globals)
__device__ __align__(16) signed char g_qn8[N_TOT * C_DIM]; // q int8*256
__device__ __align__(16) signed char g_kn8[N_TOT * C_DIM]; // k int8*256
__device__ float g_lpos[N_TOT];                             // l_pos logit (fp32, scaled)
__device__ unsigned long long g_acc;                        // fixed-point loss sum
__device__ unsigned int       g_done;                       // block completion ctr

__device__ __forceinline__ signed char q8(float v) {
    int iv = __float2int_rn(v * Q8);
    iv = max(-127, min(127, iv));
    return (signed char)iv;
}

// ---------------------------------------------------------------------------
// Kernel 1: normalize q,k over C, transpose [B,C,HW] -> [N,C] int8, and
// compute l_pos = (qn . kn) / T in fp32 while both tiles are resident.
// grid = 256 tiles of 16 positions, block = (16,16).
// ---------------------------------------------------------------------------
__global__ void __launch_bounds__(256) norm_transpose_kernel(
    const float* __restrict__ fq, const float* __restrict__ fk)
{
    if (blockIdx.x == 0 && threadIdx.x == 0 && threadIdx.y == 0)
        g_acc = 0ull;

    const int n0  = blockIdx.x * 16;      // 16 | 1024, tile never crosses batch
    const int b   = n0 / HW;
    const int hw0 = n0 % HW;
    const int tx  = threadIdx.x;          // 0..15 : hw within tile
    const int ty  = threadIdx.y;          // 0..15

    __shared__ float tq[C_DIM][17];       // [c][hw], padded
    __shared__ float tk[C_DIM][17];
    __shared__ float ssq[16][16], ssk[16][16], sdt[16][16];
    __shared__ float sinvq[16], sinvk[16];

    const size_t boff = (size_t)b * C_DIM * HW + hw0 + tx;
    const float* bq = fq + boff;
    const float* bk = fk + boff;

    float aq = 0.f, ak = 0.f, ad = 0.f;
    #pragma unroll
    for (int cc = 0; cc < 16; cc++) {
        int c = cc * 16 + ty;
        float vq = bq[(size_t)c * HW];    // 64B coalesced across tx
        float vk = bk[(size_t)c * HW];
        tq[c][tx] = vq;
        tk[c][tx] = vk;
        aq += vq * vq;
        ak += vk * vk;
        ad += vq * vk;
    }
    ssq[ty][tx] = aq;
    ssk[ty][tx] = ak;
    sdt[ty][tx] = ad;
    __syncthreads();

    if (ty == 0) {
        float sq = 0.f, sk = 0.f, sd = 0.f;
        #pragma unroll
        for (int r = 0; r < 16; r++) {
            sq += ssq[r][tx];
            sk += ssk[r][tx];
            sd += sdt[r][tx];
        }
        float iq = rsqrtf(fmaxf(sq, 1e-24f));   // 1/max(||q||,1e-12)
        float ik = rsqrtf(fmaxf(sk, 1e-24f));
        sinvq[tx] = iq;
        sinvk[tx] = ik;
        g_lpos[n0 + tx] = sd * iq * ik * INV_T; // fp32 positive logit
    }
    __syncthreads();

    const int c = ty * 16 + tx;           // thread owns one channel == linear tid
    #pragma unroll
    for (int r = 0; r < 16; r++) {
        size_t o = (size_t)(n0 + r) * C_DIM + c;
        g_qn8[o] = q8(tq[c][r] * sinvq[r]);
        g_kn8[o] = q8(tk[c][r] * sinvk[r]);
    }
}

// ---------------------------------------------------------------------------
// Kernel 2: per-row gather-dot (int8 dp4a, 2 negatives per warp-iteration,
// 16 lanes x uint4 per row, REDUX.SYNC half-warp reduce) + logsumexp +
// fused final reduction. One block (128 thr) per position n.
// ---------------------------------------------------------------------------
__global__ void __launch_bounds__(128) patchnce_main_kernel(
    const int* __restrict__ negs, float* __restrict__ out)
{
    const int n    = blockIdx.x;
    const int tid  = threadIdx.x;
    const int lane = tid & 31;
    const int warp = tid >> 5;
    const int half = lane >> 4;           // 0 or 1: which negative of the pair
    const int hl   = lane & 15;           // lane within half

    __shared__ uint4 sq8[16];             // q row int8: 256 B = 16 uint4
    __shared__ float slog[132];           // 129 logits (0 = l_pos)
    __shared__ float red[4];

    const uint4* __restrict__ k8base = (const uint4*)g_kn8;

    if (tid < 16) sq8[tid] = ((const uint4*)(g_qn8 + (size_t)n * C_DIM))[tid];
    if (tid == 0) slog[0] = g_lpos[n];
    __syncthreads();

    const uint4 qi = sq8[hl];             // channels hl*16 .. hl*16+15 (int8)
    const unsigned m16 = half ? 0xFFFF0000u : 0x0000FFFFu;

    // 32 negatives per warp; indices fetched once, broadcast by shuffle
    int myidx = negs[(size_t)n * K_NEG + warp * 32 + lane];
    myidx += (myidx >= n) ? 1 : 0;        // self-exclusion shift

    #pragma unroll
    for (int j = 0; j < 16; j++) {        // 2 negatives per iteration
        const int idx = __shfl_sync(0xffffffffu, myidx, (j << 1) | half);
        uint4 kv = __ldg(k8base + (size_t)idx * 16 + hl);
        int d = __dp4a((int)kv.x, (int)qi.x, 0);
        d     = __dp4a((int)kv.y, (int)qi.y, d);
        d     = __dp4a((int)kv.z, (int)qi.z, d);
        d     = __dp4a((int)kv.w, (int)qi.w, d);
        int s = __reduce_add_sync(m16, d);    // 16-lane sum, ALU pipe, no smem
        if (hl == 0)
            slog[1 + warp * 32 + (j << 1) + half] = (float)s * NEG_SCALE;
    }
    __syncthreads();

    // logsumexp over 129 logits (thread 0 also covers slog[128])
    const float x     = slog[tid];
    const float extra = (tid == 0) ? slog[128] : NEG_INF;

    float mx = fmaxf(x, extra);
    #pragma unroll
    for (int o = 16; o > 0; o >>= 1)
        mx = fmaxf(mx, __shfl_xor_sync(0xffffffffu, mx, o));
    if (lane == 0) red[warp] = mx;
    __syncthreads();
    mx = fmaxf(fmaxf(red[0], red[1]), fmaxf(red[2], red[3]));
    __syncthreads();                      // WAR on red[]

    float e = expf(x - mx) + ((tid == 0) ? expf(extra - mx) : 0.f);
    #pragma unroll
    for (int o = 16; o > 0; o >>= 1) e += __shfl_xor_sync(0xffffffffu, e, o);
    if (lane == 0) red[warp] = e;
    __syncthreads();

    if (tid == 0) {
        float s = red[0] + red[1] + red[2] + red[3];
        float rowloss = mx + logf(s) - slog[0];   // >= 0 always
        unsigned long long fx =
            (unsigned long long)llrintf(rowloss * (float)FIX_SCALE);
        atomicAdd(&g_acc, fx);            // integer atomics commute: deterministic
        __threadfence();
        unsigned int t = atomicAdd(&g_done, 1u);
        if (t == (unsigned int)(gridDim.x - 1)) {
            unsigned long long total = atomicAdd(&g_acc, 0ull);
            out[0] = (float)((double)total * (1.0 / FIX_SCALE) * (1.0 / N_TOT));
            g_done = 0u;                  // reset for next graph replay
        }
    }
}

// ---------------------------------------------------------------------------
extern "C" void kernel_launch(void* const* d_in, const int* in_sizes, int n_in,
                              void* d_out, int out_size)
{
    const float* fq   = (const float*)d_in[0];
    const float* fk   = (const float*)d_in[1];
    const int*   negs = (const int*)d_in[2];
    float*       out  = (float*)d_out;

    norm_transpose_kernel<<<256, dim3(16, 16)>>>(fq, fk);
    patchnce_main_kernel<<<N_TOT, 128>>>(negs, out);
}